// round 12
// baseline (speedup 1.0000x reference)
#include <cuda_runtime.h>
#include <cuda_bf16.h>
#include <stdint.h>

#define NNODES 8192
#define DIM    256
#define ALPHA  3.0f
#define NEG    0.2f

#define TPB   256                // threads per block
#define CPT   (NNODES / TPB)     // 32 columns per thread
#define VEC4  (CPT / 4)          // 8 float4 groups per thread

#define SCORE_BLOCKS 256         // must be <= guaranteed wave-1 residency
#define NODES_PER_SB (NNODES / (SCORE_BLOCKS * 16))   // 2 rounds of 16 half-warps

// Scratch (__device__ globals; zero-init at load; no cudaMalloc)
__device__ float g_s1[NNODES];
__device__ float g_s2p[NNODES];  // permuted: g_s2p[idx[j]] = s2[j]
__device__ int   g_done;         // score blocks finished (reset each launch)
__device__ int   g_fin;          // blocks fully finished  (reset each launch)

// Single-op hardware tanh (sm_75+): MUFU.TANH, rel err ~2^-11
__device__ __forceinline__ float htanh(float x) {
    float y;
    asm("tanh.approx.f32 %0, %1;" : "=f"(y) : "f"(x));
    return y;
}

// ---------------------------------------------------------------------------
// Fused kernel. Phase 1 (blocks 0..255): score for 32 nodes each, release.
// Spin barrier on g_done. Phase 2 (all 8192 blocks): R9 softmax body, row=bid.
// Counters self-reset after all blocks pass the spin (graph-replay safe).
// ---------------------------------------------------------------------------
__global__ void __launch_bounds__(TPB)
fused_kernel(const int* __restrict__ idx,
             const float* __restrict__ e1,
             const float* __restrict__ e2,
             const float* __restrict__ w,
             const float* __restrict__ att_b,
             float* __restrict__ out)
{
    const int bid = blockIdx.x;
    const int t   = threadIdx.x;

    // ---- phase 1: score (first SCORE_BLOCKS blocks only) ----
    if (bid < SCORE_BLOCKS) {
        const int hw  = t >> 4;          // half-warp id 0..15
        const int sub = t & 15;
        #pragma unroll
        for (int r = 0; r < NODES_PER_SB; r++) {
            const int node = bid * 16 + hw + r * (SCORE_BLOCKS * 16);
            const int src  = __ldg(&idx[node]);

            const float4* r1 = (const float4*)(e1 + (size_t)src * DIM);
            const float4* r2 = (const float4*)(e2 + (size_t)src * DIM);
            const float4* w1 = (const float4*)(w);
            const float4* w2 = (const float4*)(w + DIM);

            float p1 = 0.f, p2 = 0.f;
            #pragma unroll
            for (int q = 0; q < 4; q++) {
                const int k = sub + 16 * q;          // interleaved -> coalesced
                float4 a  = r1[k];
                float4 b  = r2[k];
                float4 wa = __ldg(&w1[k]);
                float4 wb = __ldg(&w2[k]);
                p1 += htanh(ALPHA * a.x) * wa.x + htanh(ALPHA * a.y) * wa.y
                    + htanh(ALPHA * a.z) * wa.z + htanh(ALPHA * a.w) * wa.w;
                p2 += htanh(ALPHA * b.x) * wb.x + htanh(ALPHA * b.y) * wb.y
                    + htanh(ALPHA * b.z) * wb.z + htanh(ALPHA * b.w) * wb.w;
            }
            #pragma unroll
            for (int o = 8; o > 0; o >>= 1) {
                p1 += __shfl_xor_sync(0xffffffffu, p1, o);
                p2 += __shfl_xor_sync(0xffffffffu, p2, o);
            }
            if (sub == 0) {
                g_s1[node] = p1;
                g_s2p[src] = p2;
            }
        }
        __syncthreads();
        __threadfence();                         // release s1/s2p
        if (t == 0) atomicAdd(&g_done, 1);
    }

    // ---- spin barrier: wait for all score blocks ----
    if (t == 0) {
        volatile int* done = &g_done;
        while (*done < SCORE_BLOCKS) __nanosleep(64);
    }
    __syncthreads();
    __threadfence();                             // acquire s1/s2p

    // ---- phase 2: softmax row i = bid (R9 measured-best body) ----
    const int i = bid;
    const float base = g_s1[i] + att_b[0];
    const float4* s2p4 = (const float4*)g_s2p;

    float vals[CPT];
    float sum = 0.f;
    #pragma unroll
    for (int q = 0; q < VEC4; q++) {
        float4 s = __ldg(&s2p4[q * TPB + t]);
        #pragma unroll
        for (int u = 0; u < 4; u++) {
            float x = base + ((const float*)&s)[u];
            x = (x > 0.f) ? x : NEG * x;         // leaky_relu
            float e = __expf(x);
            vals[q * 4 + u] = e;
            sum += e;
        }
    }

    __shared__ float shs[TPB / 32];
    #pragma unroll
    for (int o = 16; o > 0; o >>= 1)
        sum += __shfl_xor_sync(0xffffffffu, sum, o);
    if ((t & 31) == 0) shs[t >> 5] = sum;
    __syncthreads();
    sum = 0.f;
    #pragma unroll
    for (int wgi = 0; wgi < TPB / 32; wgi++) sum += shs[wgi];

    const float inv = __frcp_rn(sum);

    float4* row4 = (float4*)(out + (size_t)i * NNODES);
    #pragma unroll
    for (int q = 0; q < VEC4; q++) {
        float4 v;
        v.x = vals[q * 4 + 0] * inv;
        v.y = vals[q * 4 + 1] * inv;
        v.z = vals[q * 4 + 2] * inv;
        v.w = vals[q * 4 + 3] * inv;
        row4[q * TPB + t] = v;
    }

    // ---- epilogue: last block to finish resets counters (replay-safe) ----
    __syncthreads();
    if (t == 0) {
        __threadfence();
        int f = atomicAdd(&g_fin, 1);
        if (f == NNODES - 1) {                   // everyone passed the spin
            atomicExch(&g_done, 0);
            atomicExch(&g_fin, 0);
        }
    }
}

// ---------------------------------------------------------------------------
// Inputs: idx[int32 N], emb1_w[f32 N*D], emb2_w[f32 N*D], att_w[f32 2D],
//         att_b[f32 1].  Output: f32 N*N.
// ---------------------------------------------------------------------------
extern "C" void kernel_launch(void* const* d_in, const int* in_sizes, int n_in,
                              void* d_out, int out_size)
{
    const int*   idx  = (const int*)  d_in[0];
    const float* e1   = (const float*)d_in[1];
    const float* e2   = (const float*)d_in[2];
    const float* attw = (const float*)d_in[3];
    const float* attb = (const float*)d_in[4];
    float*       out  = (float*)d_out;

    fused_kernel<<<NNODES, TPB>>>(idx, e1, e2, attw, attb, out);
}

// round 13
// speedup vs baseline: 2.2495x; 2.2495x over previous
#include <cuda_runtime.h>
#include <cuda_bf16.h>
#include <stdint.h>

#define NNODES 8192
#define DIM    256
#define ALPHA  3.0f
#define NEG    0.2f

#define TPB  256                 // softmax threads per block (measured-best R9)
#define CPT  (NNODES / TPB)      // 32 columns per thread
#define VEC4 (CPT / 4)           // 8 float4 groups per thread

// Scratch (__device__ globals; no cudaMalloc allowed)
__device__ float g_s1[NNODES];
__device__ float g_s2p[NNODES];  // permuted: g_s2p[idx[j]] = s2[j]

// Single-op hardware tanh (sm_75+): MUFU.TANH, rel err ~2^-11 (<< 1e-3 budget)
__device__ __forceinline__ float htanh(float x) {
    float y;
    asm("tanh.approx.f32 %0, %1;" : "=f"(y) : "f"(x));
    return y;
}

// ---------------------------------------------------------------------------
// score: HALF-WARP per node (16 lanes x 16 dims each) — byte-identical to R9.
// ---------------------------------------------------------------------------
__global__ void __launch_bounds__(128)
score_kernel(const int* __restrict__ idx,
             const float* __restrict__ e1,
             const float* __restrict__ e2,
             const float* __restrict__ w)
{
    const int node = (blockIdx.x * 128 + threadIdx.x) >> 4;
    const int sub  = threadIdx.x & 15;
    const int src  = __ldg(&idx[node]);

    const float4* r1 = (const float4*)(e1 + (size_t)src * DIM);
    const float4* r2 = (const float4*)(e2 + (size_t)src * DIM);
    const float4* w1 = (const float4*)(w);
    const float4* w2 = (const float4*)(w + DIM);

    float p1 = 0.f, p2 = 0.f;
    #pragma unroll
    for (int q = 0; q < 4; q++) {
        const int k = sub + 16 * q;                 // interleaved -> coalesced
        float4 a  = r1[k];
        float4 b  = r2[k];
        float4 wa = __ldg(&w1[k]);
        float4 wb = __ldg(&w2[k]);
        p1 += htanh(ALPHA * a.x) * wa.x + htanh(ALPHA * a.y) * wa.y
            + htanh(ALPHA * a.z) * wa.z + htanh(ALPHA * a.w) * wa.w;
        p2 += htanh(ALPHA * b.x) * wb.x + htanh(ALPHA * b.y) * wb.y
            + htanh(ALPHA * b.z) * wb.z + htanh(ALPHA * b.w) * wb.w;
    }
    #pragma unroll
    for (int o = 8; o > 0; o >>= 1) {
        p1 += __shfl_xor_sync(0xffffffffu, p1, o);
        p2 += __shfl_xor_sync(0xffffffffu, p2, o);
    }
    if (sub == 0) {
        g_s1[node] = p1;
        g_s2p[src] = p2;
    }
}

// ---------------------------------------------------------------------------
// softmax: one block per row i — R9 measured-best body, plus PDL guard.
// Blocks may launch while score_kernel drains; cudaGridDependencySynchronize
// blocks until the upstream kernel (score) has fully completed, after which
// g_s1/g_s2p reads are safe.
// ---------------------------------------------------------------------------
__global__ void __launch_bounds__(TPB)
softmax_kernel(const float* __restrict__ att_b,
               float* __restrict__ out)
{
    const int i = blockIdx.x;
    const int t = threadIdx.x;

    // pre-dependency prologue: pure address math / parameter loads
    const float bias   = __ldg(att_b);
    float4*     row4   = (float4*)(out + (size_t)i * NNODES);
    const float4* s2p4 = (const float4*)g_s2p;

    // wait for score_kernel completion (PDL); no-op if launched normally
    cudaGridDependencySynchronize();

    const float base = g_s1[i] + bias;

    float vals[CPT];
    float sum = 0.f;
    #pragma unroll
    for (int q = 0; q < VEC4; q++) {
        float4 s = __ldg(&s2p4[q * TPB + t]);
        #pragma unroll
        for (int u = 0; u < 4; u++) {
            float x = base + ((const float*)&s)[u];
            x = (x > 0.f) ? x : NEG * x;      // leaky_relu
            float e = __expf(x);
            vals[q * 4 + u] = e;
            sum += e;
        }
    }

    // block sum (8 warps)
    __shared__ float shs[TPB / 32];
    #pragma unroll
    for (int o = 16; o > 0; o >>= 1)
        sum += __shfl_xor_sync(0xffffffffu, sum, o);
    if ((t & 31) == 0) shs[t >> 5] = sum;
    __syncthreads();
    sum = 0.f;
    #pragma unroll
    for (int wgi = 0; wgi < TPB / 32; wgi++) sum += shs[wgi];

    const float inv = __frcp_rn(sum);

    // contiguous float4 stores (plain, cached)
    #pragma unroll
    for (int q = 0; q < VEC4; q++) {
        float4 v;
        v.x = vals[q * 4 + 0] * inv;
        v.y = vals[q * 4 + 1] * inv;
        v.z = vals[q * 4 + 2] * inv;
        v.w = vals[q * 4 + 3] * inv;
        row4[q * TPB + t] = v;
    }
}

// ---------------------------------------------------------------------------
// Inputs: idx[int32 N], emb1_w[f32 N*D], emb2_w[f32 N*D], att_w[f32 2D],
//         att_b[f32 1].  Output: f32 N*N.
// ---------------------------------------------------------------------------
extern "C" void kernel_launch(void* const* d_in, const int* in_sizes, int n_in,
                              void* d_out, int out_size)
{
    const int*   idx  = (const int*)  d_in[0];
    const float* e1   = (const float*)d_in[1];
    const float* e2   = (const float*)d_in[2];
    const float* attw = (const float*)d_in[3];
    const float* attb = (const float*)d_in[4];
    float*       out  = (float*)d_out;

    score_kernel<<<NNODES * 16 / 128, 128>>>(idx, e1, e2, attw);

    // Programmatic dependent launch: let softmax blocks spin up while the
    // score kernel drains; the device-side sync enforces the data dependency.
    cudaLaunchConfig_t cfg = {};
    cfg.gridDim  = dim3(NNODES, 1, 1);
    cfg.blockDim = dim3(TPB, 1, 1);
    cfg.dynamicSmemBytes = 0;
    cudaLaunchAttribute attr[1];
    attr[0].id = cudaLaunchAttributeProgrammaticStreamSerialization;
    attr[0].val.programmaticStreamSerializationAllowed = 1;
    cfg.attrs    = attr;
    cfg.numAttrs = 1;
    cudaError_t err = cudaLaunchKernelEx(&cfg, softmax_kernel, attb, out);
    if (err != cudaSuccess) {
        // fallback: plain launch (identical semantics)
        softmax_kernel<<<NNODES, TPB>>>(attb, out);
    }
}